// round 6
// baseline (speedup 1.0000x reference)
#include <cuda_runtime.h>
#include <math.h>

#define BB 8
#define SS 4096
#define VV 256
#define DD 512
#define WW 2048          // S / STRIDE
#define DIM 128
#define N2 4096          // B * (1024/2)
#define N3 1024          // B * (256/2)
#define L2C 1024
#define L3C 256
#define INV_TEMP (1.0f/0.07f)
#define SPACE_TOK 63

// ---- scratch (no allocations allowed) ----
__device__ double g_acc[7*16];       // 128B-spaced accumulators
// 0:ce*mask 16:mask 32:ce 48:word_tot 64:word_cnt 80:nce2 96:nce3
__device__ int    g_sp[BB][SS+4];    // space positions, rank-indexed from 1
__device__ int    g_nsp[BB];
__device__ float  g_aN2[N2*DIM];     // a_hat / temp, row-major
__device__ float  g_pT2[DIM*N2];     // p_hat transposed (dim-major)
__device__ float  g_diag2[N2];
__device__ float  g_aN3[N3*DIM];
__device__ float  g_pT3[DIM*N3];
__device__ float  g_diag3[N3];

__global__ void k_init() {
    if (threadIdx.x < 7*16) g_acc[threadIdx.x] = 0.0;
}

// ---------------- char cross-entropy: one warp per (b,s) row ----------------
__global__ void k_ce(const float* __restrict__ logits,
                     const int*   __restrict__ tg,
                     const float* __restrict__ mask) {
    int gw   = (blockIdx.x * blockDim.x + threadIdx.x) >> 5;   // row id, grid exact
    int lane = threadIdx.x & 31;
    int wib  = threadIdx.x >> 5;

    const float4* row = (const float4*)(logits + (size_t)gw * VV);
    float4 v0 = row[lane];
    float4 v1 = row[lane + 32];
    float m = fmaxf(fmaxf(fmaxf(v0.x,v0.y),fmaxf(v0.z,v0.w)),
                    fmaxf(fmaxf(v1.x,v1.y),fmaxf(v1.z,v1.w)));
    #pragma unroll
    for (int o = 16; o; o >>= 1) m = fmaxf(m, __shfl_xor_sync(0xffffffffu, m, o));
    float s = __expf(v0.x-m)+__expf(v0.y-m)+__expf(v0.z-m)+__expf(v0.w-m)
            + __expf(v1.x-m)+__expf(v1.y-m)+__expf(v1.z-m)+__expf(v1.w-m);
    #pragma unroll
    for (int o = 16; o; o >>= 1) s += __shfl_xor_sync(0xffffffffu, s, o);

    __shared__ float sh_cem[8], sh_mk[8], sh_ce[8];
    if (lane == 0) {
        float lse = m + logf(s);
        int   t   = tg[gw];
        float lt  = logits[(size_t)gw * VV + t];
        float ce  = lse - lt;
        float mk  = mask[gw];
        sh_cem[wib] = ce * mk;  sh_mk[wib] = mk;  sh_ce[wib] = ce;
    }
    __syncthreads();
    if (threadIdx.x == 0) {
        float a = 0.f, bm = 0.f, c = 0.f;
        #pragma unroll
        for (int i = 0; i < 8; i++) { a += sh_cem[i]; bm += sh_mk[i]; c += sh_ce[i]; }
        atomicAdd(&g_acc[0],  (double)a);
        atomicAdd(&g_acc[16], (double)bm);
        atomicAdd(&g_acc[32], (double)c);
    }
}

// ---------------- space-position scan: one block per batch ----------------
__global__ void k_scan(const int* __restrict__ tg) {
    int b = blockIdx.x, tid = threadIdx.x;
    const int CH = SS / 256;                       // 16 elems/thread
    const int* t = tg + b * SS;
    int base = tid * CH;
    int flags[CH]; int local = 0;
    #pragma unroll
    for (int e = 0; e < CH; e++) { flags[e] = (t[base+e] == SPACE_TOK); local += flags[e]; }

    __shared__ int sc[256];
    sc[tid] = local; __syncthreads();
    for (int off = 1; off < 256; off <<= 1) {
        int v = (tid >= off) ? sc[tid - off] : 0;
        __syncthreads();
        sc[tid] += v;
        __syncthreads();
    }
    int incl = sc[tid];
    int run  = incl - local;                       // exclusive prefix
    #pragma unroll
    for (int e = 0; e < CH; e++) {
        if (flags[e]) { run++; g_sp[b][run] = base + e; }
    }
    if (tid == 255) g_nsp[b] = incl;
}

// ---------------- word span loss: block per (b, segment-slot) ----------------
__global__ void k_word(const float* __restrict__ wp, const float* __restrict__ cf) {
    int b = blockIdx.x;
    int nsp = g_nsp[b];
    int tid = threadIdx.x;
    int w = tid >> 5, lane = tid & 31;
    __shared__ float sh[4];

    for (int k = blockIdx.y + 1; k <= nsp - 1; k += gridDim.y) {
        int p0 = g_sp[b][k], p1 = g_sp[b][k+1];
        int t0 = p0 + 1, len = p1 - p0 - 1;
        bool valid = (len > 0) && ((p0 >> 1) < WW);         // uniform across block
        if (valid) {
            int wpi = p0 >> 1;
            if (wpi > WW-1) wpi = WW-1;
            float wsum = 0.f;
            for (int d = w; d < DD; d += 4) {
                const float* fr = cf + ((size_t)b * DD + d) * SS;
                float s = 0.f;
                for (int q = lane; q < len; q += 32) s += fr[t0 + q];
                #pragma unroll
                for (int o = 16; o; o >>= 1) s += __shfl_xor_sync(0xffffffffu, s, o);
                if (lane == 0) {
                    float mean = s / (float)len;
                    float pr = wp[((size_t)b * DD + d) * WW + wpi];
                    float df = pr - mean;
                    wsum += df * df;
                }
            }
            if (lane == 0) sh[w] = wsum;
            __syncthreads();
            if (tid == 0) {
                float mse = (sh[0] + sh[1] + sh[2] + sh[3]) / (float)DD;
                atomicAdd(&g_acc[48], (double)mse);
                atomicAdd(&g_acc[64], 1.0);
            }
            __syncthreads();
        }
    }
}

// ---------------- info_nce normalization: one warp per pair ----------------
__global__ void k_nrm(const float* __restrict__ emb, int n, int npair, int L, int which) {
    float* aN = which ? g_aN3 : g_aN2;
    float* pT = which ? g_pT3 : g_pT2;
    float* dg = which ? g_diag3 : g_diag2;
    int gw   = (blockIdx.x * blockDim.x + threadIdx.x) >> 5;
    int lane = threadIdx.x & 31;
    if (gw >= n) return;
    int b = gw / npair, j = gw % npair;
    const float* base = emb + (size_t)b * DIM * L + 2 * j;

    float av[4], pv[4];
    float na = 0.f, npw = 0.f;
    #pragma unroll
    for (int q = 0; q < 4; q++) {
        int d = lane + 32 * q;
        av[q] = base[(size_t)d * L];
        pv[q] = base[(size_t)d * L + 1];
        na  += av[q] * av[q];
        npw += pv[q] * pv[q];
    }
    #pragma unroll
    for (int o = 16; o; o >>= 1) {
        na  += __shfl_xor_sync(0xffffffffu, na,  o);
        npw += __shfl_xor_sync(0xffffffffu, npw, o);
    }
    float ia = 1.f / fmaxf(sqrtf(na),  1e-12f);
    float ip = 1.f / fmaxf(sqrtf(npw), 1e-12f);
    float dot = 0.f;
    #pragma unroll
    for (int q = 0; q < 4; q++) {
        float ah = av[q] * ia, ph = pv[q] * ip;
        dot += ah * ph;
        int d = lane + 32 * q;
        aN[(size_t)gw * DIM + d] = ah * INV_TEMP;   // pre-scale by 1/temp
        pT[(size_t)d * n + gw]   = ph;
    }
    #pragma unroll
    for (int o = 16; o; o >>= 1) dot += __shfl_xor_sync(0xffffffffu, dot, o);
    if (lane == 0) dg[gw] = dot * INV_TEMP;
}

// ------- info_nce main: 8 rows/block, fused GEMM + exp-sum (no logits matrix) -------
__global__ void k_nce(int n, int which, int slot) {
    const float*  aN  = which ? g_aN3 : g_aN2;
    const float4* pT4 = (const float4*)(which ? g_pT3 : g_pT2);
    const float*  dg  = which ? g_diag3 : g_diag2;
    int i0 = blockIdx.x * 8;
    int tid = threadIdx.x;

    __shared__ float a_sh[8 * DIM];
    __shared__ float red[256];
    for (int idx = tid; idx < 8 * DIM; idx += 256)
        a_sh[idx] = aN[(size_t)i0 * DIM + idx];
    __syncthreads();

    float part[8];
    #pragma unroll
    for (int r = 0; r < 8; r++) part[r] = 0.f;

    int n4 = n >> 2;
    for (int jj = tid; jj < n4; jj += 256) {
        float acc[8][4];
        #pragma unroll
        for (int r = 0; r < 8; r++) { acc[r][0]=acc[r][1]=acc[r][2]=acc[r][3]=0.f; }

        #pragma unroll 4
        for (int d = 0; d < DIM; d += 4) {
            float4 p0 = pT4[(size_t)(d+0) * n4 + jj];
            float4 p1 = pT4[(size_t)(d+1) * n4 + jj];
            float4 p2 = pT4[(size_t)(d+2) * n4 + jj];
            float4 p3 = pT4[(size_t)(d+3) * n4 + jj];
            #pragma unroll
            for (int r = 0; r < 8; r++) {
                float4 a = *(const float4*)&a_sh[r * DIM + d];
                acc[r][0] = fmaf(a.x, p0.x, fmaf(a.y, p1.x, fmaf(a.z, p2.x, fmaf(a.w, p3.x, acc[r][0]))));
                acc[r][1] = fmaf(a.x, p0.y, fmaf(a.y, p1.y, fmaf(a.z, p2.y, fmaf(a.w, p3.y, acc[r][1]))));
                acc[r][2] = fmaf(a.x, p0.z, fmaf(a.y, p1.z, fmaf(a.z, p2.z, fmaf(a.w, p3.z, acc[r][2]))));
                acc[r][3] = fmaf(a.x, p0.w, fmaf(a.y, p1.w, fmaf(a.z, p2.w, fmaf(a.w, p3.w, acc[r][3]))));
            }
        }
        // logits in [-14.3, 14.3] -> exp-sum fits fp32 without max pass
        #pragma unroll
        for (int r = 0; r < 8; r++)
            part[r] += __expf(acc[r][0]) + __expf(acc[r][1]) + __expf(acc[r][2]) + __expf(acc[r][3]);
    }

    #pragma unroll
    for (int r = 0; r < 8; r++) {
        red[tid] = part[r]; __syncthreads();
        for (int s = 128; s; s >>= 1) { if (tid < s) red[tid] += red[tid + s]; __syncthreads(); }
        if (tid == 0) {
            double contrib = log((double)red[0]) - (double)dg[i0 + r];
            atomicAdd(&g_acc[slot], contrib);
        }
        __syncthreads();
    }
}

// ---------------- combine ----------------
__global__ void k_final(float* out) {
    double nm    = g_acc[16];
    double charl = (nm > 0.0) ? (g_acc[0] / fmax(nm, 1.0))
                              : (g_acc[32] / (double)(BB * SS));
    double wcnt  = g_acc[64];
    double wordl = (wcnt > 0.0) ? (g_acc[48] / fmax(wcnt, 1.0)) : 0.0;
    double ph    = g_acc[80] / (double)N2;
    double id    = g_acc[96] / (double)N3;
    out[0] = (float)(1.0 * charl + 0.5 * wordl + 0.1 * ph + 0.1 * id);
}

extern "C" void kernel_launch(void* const* d_in, const int* in_sizes, int n_in,
                              void* d_out, int out_size) {
    const float* logits        = (const float*)d_in[0];
    const float* word_preds    = (const float*)d_in[1];
    const float* char_features = (const float*)d_in[2];
    const float* c2            = (const float*)d_in[3];
    const float* c3            = (const float*)d_in[4];
    const int*   targets       = (const int*)  d_in[5];
    const float* mask          = (const float*)d_in[6];
    float* out = (float*)d_out;

    k_init <<<1, 128>>>();
    k_ce   <<<(BB * SS) / 8, 256>>>(logits, targets, mask);
    k_scan <<<BB, 256>>>(targets);
    k_word <<<dim3(BB, 64), 128>>>(word_preds, char_features);
    k_nrm  <<<(N2 + 7) / 8, 256>>>(c2, N2, L2C / 2, L2C, 0);
    k_nrm  <<<(N3 + 7) / 8, 256>>>(c3, N3, L3C / 2, L3C, 1);
    k_nce  <<<N2 / 8, 256>>>(N2, 0, 80);
    k_nce  <<<N3 / 8, 256>>>(N3, 1, 96);
    k_final<<<1, 1>>>(out);
}

// round 7
// speedup vs baseline: 3.2120x; 3.2120x over previous
#include <cuda_runtime.h>
#include <math.h>

#define BB 8
#define SS 4096
#define VV 256
#define DD 512
#define WW 2048          // S / STRIDE
#define DIM 128
#define N2 4096          // B * (1024/2)
#define N3 1024          // B * (256/2)
#define L2C 1024
#define L3C 256
#define INV_TEMP (1.0f/0.07f)
#define SPACE_TOK 63

// ---- scratch (no allocations allowed) ----
__device__ double g_acc[7*16];       // 128B-spaced accumulators
// 0:ce*mask 16:mask 32:ce 48:word_tot 64:word_cnt 80:nce2 96:nce3
__device__ int    g_sp[BB][SS+4];    // space positions, rank-indexed from 1
__device__ int    g_nsp[BB];
__device__ float  g_aN2[N2*DIM];     // a_hat / temp, row-major
__device__ float  g_pT2[DIM*N2];     // p_hat transposed (dim-major)
__device__ float  g_diag2[N2];
__device__ float  g_aN3[N3*DIM];
__device__ float  g_pT3[DIM*N3];
__device__ float  g_diag3[N3];

__global__ void k_init() {
    if (threadIdx.x < 7*16) g_acc[threadIdx.x] = 0.0;
}

// ---------------- char cross-entropy: one warp per (b,s) row ----------------
__global__ void k_ce(const float* __restrict__ logits,
                     const int*   __restrict__ tg,
                     const float* __restrict__ mask) {
    int gw   = (blockIdx.x * blockDim.x + threadIdx.x) >> 5;   // row id, grid exact
    int lane = threadIdx.x & 31;
    int wib  = threadIdx.x >> 5;

    const float4* row = (const float4*)(logits + (size_t)gw * VV);
    float4 v0 = row[lane];
    float4 v1 = row[lane + 32];
    float m = fmaxf(fmaxf(fmaxf(v0.x,v0.y),fmaxf(v0.z,v0.w)),
                    fmaxf(fmaxf(v1.x,v1.y),fmaxf(v1.z,v1.w)));
    #pragma unroll
    for (int o = 16; o; o >>= 1) m = fmaxf(m, __shfl_xor_sync(0xffffffffu, m, o));
    float s = __expf(v0.x-m)+__expf(v0.y-m)+__expf(v0.z-m)+__expf(v0.w-m)
            + __expf(v1.x-m)+__expf(v1.y-m)+__expf(v1.z-m)+__expf(v1.w-m);
    #pragma unroll
    for (int o = 16; o; o >>= 1) s += __shfl_xor_sync(0xffffffffu, s, o);

    __shared__ float sh_cem[8], sh_mk[8], sh_ce[8];
    if (lane == 0) {
        float lse = m + logf(s);
        int   t   = tg[gw];
        float lt  = logits[(size_t)gw * VV + t];
        float ce  = lse - lt;
        float mk  = mask[gw];
        sh_cem[wib] = ce * mk;  sh_mk[wib] = mk;  sh_ce[wib] = ce;
    }
    __syncthreads();
    if (threadIdx.x == 0) {
        float a = 0.f, bm = 0.f, c = 0.f;
        #pragma unroll
        for (int i = 0; i < 8; i++) { a += sh_cem[i]; bm += sh_mk[i]; c += sh_ce[i]; }
        atomicAdd(&g_acc[0],  (double)a);
        atomicAdd(&g_acc[16], (double)bm);
        atomicAdd(&g_acc[32], (double)c);
    }
}

// ---------------- space-position scan: one block per batch ----------------
__global__ void k_scan(const int* __restrict__ tg) {
    int b = blockIdx.x, tid = threadIdx.x;
    const int CH = SS / 256;                       // 16 elems/thread
    const int* t = tg + b * SS;
    int base = tid * CH;
    int flags[CH]; int local = 0;
    #pragma unroll
    for (int e = 0; e < CH; e++) { flags[e] = (t[base+e] == SPACE_TOK); local += flags[e]; }

    __shared__ int sc[256];
    sc[tid] = local; __syncthreads();
    for (int off = 1; off < 256; off <<= 1) {
        int v = (tid >= off) ? sc[tid - off] : 0;
        __syncthreads();
        sc[tid] += v;
        __syncthreads();
    }
    int incl = sc[tid];
    int run  = incl - local;                       // exclusive prefix
    #pragma unroll
    for (int e = 0; e < CH; e++) {
        if (flags[e]) { run++; g_sp[b][run] = base + e; }
    }
    if (tid == 255) g_nsp[b] = incl;
}

// ---------------- word span loss: one warp per (b,d) row ----------------
// Inverted loop nest vs the previous version: 4096 warps (one per cf row),
// each walks the ~15 segments of its batch. (pred-mean)^2 is lane-uniform,
// so no cross-d reduction is needed; block reduce + 1 atomic per block.
__global__ void k_word(const float* __restrict__ wp, const float* __restrict__ cf) {
    int gw   = (blockIdx.x * blockDim.x + threadIdx.x) >> 5;   // 0..4095
    int lane = threadIdx.x & 31;
    int wib  = threadIdx.x >> 5;
    int b = gw >> 9;          // / DD
    int d = gw & (DD - 1);
    int nsp = g_nsp[b];

    const float* fr   = cf + ((size_t)b * DD + d) * SS;
    const float* wrow = wp + ((size_t)b * DD + d) * WW;

    float tot = 0.f;
    int   cnt = 0;
    for (int k = 1; k <= nsp - 1; k++) {
        int p0  = g_sp[b][k];
        int p1  = g_sp[b][k + 1];
        int len = p1 - p0 - 1;
        int wpi = p0 >> 1;
        if (len > 0 && wpi < WW) {
            const float* seg = fr + p0 + 1;
            float s = 0.f;
            for (int q = lane; q < len; q += 32) s += seg[q];
            #pragma unroll
            for (int o = 16; o; o >>= 1) s += __shfl_xor_sync(0xffffffffu, s, o);
            float mean = s / (float)len;
            float df = wrow[wpi] - mean;
            tot += df * df;        // lane-uniform
            cnt++;
        }
    }

    __shared__ float sh_t[8];
    __shared__ int   sh_c[8];
    if (lane == 0) { sh_t[wib] = tot; sh_c[wib] = (d == 0) ? cnt : 0; }
    __syncthreads();
    if (threadIdx.x == 0) {
        float a = 0.f; int c = 0;
        #pragma unroll
        for (int i = 0; i < 8; i++) { a += sh_t[i]; c += sh_c[i]; }
        atomicAdd(&g_acc[48], (double)a / (double)DD);
        if (c) atomicAdd(&g_acc[64], (double)c);
    }
}

// ---------------- info_nce normalization: one warp per pair ----------------
__global__ void k_nrm(const float* __restrict__ emb, int n, int npair, int L, int which) {
    float* aN = which ? g_aN3 : g_aN2;
    float* pT = which ? g_pT3 : g_pT2;
    float* dg = which ? g_diag3 : g_diag2;
    int gw   = (blockIdx.x * blockDim.x + threadIdx.x) >> 5;
    int lane = threadIdx.x & 31;
    if (gw >= n) return;
    int b = gw / npair, j = gw % npair;
    const float* base = emb + (size_t)b * DIM * L + 2 * j;

    float av[4], pv[4];
    float na = 0.f, npw = 0.f;
    #pragma unroll
    for (int q = 0; q < 4; q++) {
        int d = lane + 32 * q;
        av[q] = base[(size_t)d * L];
        pv[q] = base[(size_t)d * L + 1];
        na  += av[q] * av[q];
        npw += pv[q] * pv[q];
    }
    #pragma unroll
    for (int o = 16; o; o >>= 1) {
        na  += __shfl_xor_sync(0xffffffffu, na,  o);
        npw += __shfl_xor_sync(0xffffffffu, npw, o);
    }
    float ia = 1.f / fmaxf(sqrtf(na),  1e-12f);
    float ip = 1.f / fmaxf(sqrtf(npw), 1e-12f);
    float dot = 0.f;
    #pragma unroll
    for (int q = 0; q < 4; q++) {
        float ah = av[q] * ia, ph = pv[q] * ip;
        dot += ah * ph;
        int d = lane + 32 * q;
        aN[(size_t)gw * DIM + d] = ah * INV_TEMP;   // pre-scale by 1/temp
        pT[(size_t)d * n + gw]   = ph;
    }
    #pragma unroll
    for (int o = 16; o; o >>= 1) dot += __shfl_xor_sync(0xffffffffu, dot, o);
    if (lane == 0) dg[gw] = dot * INV_TEMP;
}

// ------- info_nce main: 8 rows/block, fused GEMM + exp-sum (no logits matrix) -------
__global__ void k_nce(int n, int which, int slot) {
    const float*  aN  = which ? g_aN3 : g_aN2;
    const float4* pT4 = (const float4*)(which ? g_pT3 : g_pT2);
    const float*  dg  = which ? g_diag3 : g_diag2;
    int i0 = blockIdx.x * 8;
    int tid = threadIdx.x;

    __shared__ float a_sh[8 * DIM];
    __shared__ float red[256];
    for (int idx = tid; idx < 8 * DIM; idx += 256)
        a_sh[idx] = aN[(size_t)i0 * DIM + idx];
    __syncthreads();

    float part[8];
    #pragma unroll
    for (int r = 0; r < 8; r++) part[r] = 0.f;

    int n4 = n >> 2;
    for (int jj = tid; jj < n4; jj += 256) {
        float acc[8][4];
        #pragma unroll
        for (int r = 0; r < 8; r++) { acc[r][0]=acc[r][1]=acc[r][2]=acc[r][3]=0.f; }

        #pragma unroll 4
        for (int d = 0; d < DIM; d += 4) {
            float4 p0 = pT4[(size_t)(d+0) * n4 + jj];
            float4 p1 = pT4[(size_t)(d+1) * n4 + jj];
            float4 p2 = pT4[(size_t)(d+2) * n4 + jj];
            float4 p3 = pT4[(size_t)(d+3) * n4 + jj];
            #pragma unroll
            for (int r = 0; r < 8; r++) {
                float4 a = *(const float4*)&a_sh[r * DIM + d];
                acc[r][0] = fmaf(a.x, p0.x, fmaf(a.y, p1.x, fmaf(a.z, p2.x, fmaf(a.w, p3.x, acc[r][0]))));
                acc[r][1] = fmaf(a.x, p0.y, fmaf(a.y, p1.y, fmaf(a.z, p2.y, fmaf(a.w, p3.y, acc[r][1]))));
                acc[r][2] = fmaf(a.x, p0.z, fmaf(a.y, p1.z, fmaf(a.z, p2.z, fmaf(a.w, p3.z, acc[r][2]))));
                acc[r][3] = fmaf(a.x, p0.w, fmaf(a.y, p1.w, fmaf(a.z, p2.w, fmaf(a.w, p3.w, acc[r][3]))));
            }
        }
        // logits in [-14.3, 14.3] -> exp-sum fits fp32 without max pass
        #pragma unroll
        for (int r = 0; r < 8; r++)
            part[r] += __expf(acc[r][0]) + __expf(acc[r][1]) + __expf(acc[r][2]) + __expf(acc[r][3]);
    }

    #pragma unroll
    for (int r = 0; r < 8; r++) {
        red[tid] = part[r]; __syncthreads();
        for (int s = 128; s; s >>= 1) { if (tid < s) red[tid] += red[tid + s]; __syncthreads(); }
        if (tid == 0) {
            double contrib = log((double)red[0]) - (double)dg[i0 + r];
            atomicAdd(&g_acc[slot], contrib);
        }
        __syncthreads();
    }
}

// ---------------- combine ----------------
__global__ void k_final(float* out) {
    double nm    = g_acc[16];
    double charl = (nm > 0.0) ? (g_acc[0] / fmax(nm, 1.0))
                              : (g_acc[32] / (double)(BB * SS));
    double wcnt  = g_acc[64];
    double wordl = (wcnt > 0.0) ? (g_acc[48] / fmax(wcnt, 1.0)) : 0.0;
    double ph    = g_acc[80] / (double)N2;
    double id    = g_acc[96] / (double)N3;
    out[0] = (float)(1.0 * charl + 0.5 * wordl + 0.1 * ph + 0.1 * id);
}

extern "C" void kernel_launch(void* const* d_in, const int* in_sizes, int n_in,
                              void* d_out, int out_size) {
    const float* logits        = (const float*)d_in[0];
    const float* word_preds    = (const float*)d_in[1];
    const float* char_features = (const float*)d_in[2];
    const float* c2            = (const float*)d_in[3];
    const float* c3            = (const float*)d_in[4];
    const int*   targets       = (const int*)  d_in[5];
    const float* mask          = (const float*)d_in[6];
    float* out = (float*)d_out;

    k_init <<<1, 128>>>();
    k_scan <<<BB, 256>>>(targets);
    k_word <<<(BB * DD) / 8, 256>>>(word_preds, char_features);
    k_ce   <<<(BB * SS) / 8, 256>>>(logits, targets, mask);
    k_nrm  <<<(N2 + 7) / 8, 256>>>(c2, N2, L2C / 2, L2C, 0);
    k_nrm  <<<(N3 + 7) / 8, 256>>>(c3, N3, L3C / 2, L3C, 1);
    k_nce  <<<N2 / 8, 256>>>(N2, 0, 80);
    k_nce  <<<N3 / 8, 256>>>(N3, 1, 96);
    k_final<<<1, 1>>>(out);
}